// round 12
// baseline (speedup 1.0000x reference)
#include <cuda_runtime.h>
#include <cuda_fp16.h>
#include <math.h>

// ----------------------------------------------------------------------------
// OctreeRender (TensoRF tri-plane renderer) — fp16 tables, cooperative gather,
// smem partials, delta line tables, unroll-2 rounds + slim phase-1 state.
// Output: float[4096*3] rgb_map then float[4096] depth_map
// ----------------------------------------------------------------------------

#define N_RAYS    4096
#define RES       256
#define NS        256
#define DC        16
#define ACP       32    // app channels padded 24 -> 32

// fp16 channel-last scratch (zero-init; pad channels never written => 0)
__device__ __half g_dph[3 * RES * RES * DC];        // [i][y][x][16]
__device__ __half g_aph[3 * RES * RES * ACP];       // [i][y][x][32]
__device__ __half g_dlph[3 * RES * 2 * DC];         // [i][p][{L0,dL}][16]
__device__ __half g_alph[3 * RES * 2 * ACP];        // [i][p][{L0,dL}][32]

// ---------------- prep: thread-per-texel, no smem ----------------------------

__global__ __launch_bounds__(256) void prep_kernel(
    const float* __restrict__ dp, const float* __restrict__ ap,
    const float* __restrict__ dl, const float* __restrict__ al) {
    const int b = blockIdx.x;
    const int tid = threadIdx.x;

    if (b < 768) {
        const int i = b >> 8;
        const int y = b & 255;
        const int x = tid;
        float v[DC];
#pragma unroll
        for (int c = 0; c < DC; c++)
            v[c] = __ldg(&dp[((i * DC + c) * RES + y) * RES + x]);
        unsigned h[8];
#pragma unroll
        for (int k = 0; k < 8; k++) {
            __half2 t = __floats2half2_rn(v[2 * k], v[2 * k + 1]);
            h[k] = *reinterpret_cast<unsigned*>(&t);
        }
        uint4* outp = reinterpret_cast<uint4*>(g_dph) + ((i * RES + y) * RES + x) * 2;
        outp[0] = make_uint4(h[0], h[1], h[2], h[3]);
        outp[1] = make_uint4(h[4], h[5], h[6], h[7]);
    } else if (b < 1536) {
        const int bb = b - 768;
        const int i = bb >> 8;
        const int y = bb & 255;
        const int x = tid;
        float v[24];
#pragma unroll
        for (int c = 0; c < 24; c++)
            v[c] = __ldg(&ap[((i * 24 + c) * RES + y) * RES + x]);
        unsigned h[16];
#pragma unroll
        for (int k = 0; k < 12; k++) {
            __half2 t = __floats2half2_rn(v[2 * k], v[2 * k + 1]);
            h[k] = *reinterpret_cast<unsigned*>(&t);
        }
#pragma unroll
        for (int k = 12; k < 16; k++) h[k] = 0u;
        uint4* outp = reinterpret_cast<uint4*>(g_aph) + ((i * RES + y) * RES + x) * 4;
        outp[0] = make_uint4(h[0],  h[1],  h[2],  h[3]);
        outp[1] = make_uint4(h[4],  h[5],  h[6],  h[7]);
        outp[2] = make_uint4(h[8],  h[9],  h[10], h[11]);
        outp[3] = make_uint4(h[12], h[13], h[14], h[15]);
    } else {
        const int gtid = (b - 1536) * 256 + tid;   // 0..49151
        if (gtid < 3 * RES * 2 * DC) {
            const int c   = gtid & 15;
            const int pos = (gtid >> 4) & 1;
            const int p   = (gtid >> 5) & 255;
            const int i   = gtid >> 13;
            const int pp  = (p + 1 < 255) ? (p + 1) : 255;
            float l0 = __ldg(&dl[(i * DC + c) * RES + p]);
            float l1 = __ldg(&dl[(i * DC + c) * RES + pp]);
            g_dlph[gtid] = __float2half(pos ? (l1 - l0) : l0);
        }
        {
            const int c   = gtid & 31;
            const int pos = (gtid >> 5) & 1;
            const int p   = (gtid >> 6) & 255;
            const int i   = gtid >> 14;
            const int pp  = (p + 1 < 255) ? (p + 1) : 255;
            float l0 = (c < 24) ? __ldg(&al[(i * 24 + c) * RES + p])  : 0.0f;
            float l1 = (c < 24) ? __ldg(&al[(i * 24 + c) * RES + pp]) : 0.0f;
            g_alph[gtid] = __float2half(pos ? (l1 - l0) : l0);
        }
    }
}

// ---------------- render -----------------------------------------------------

__device__ __forceinline__ void grid_split(float f, float& w, int& i0) {
    float f0 = fminf(fmaxf(floorf(f), 0.0f), 254.0f);
    i0 = (int)f0;
    w  = f - f0;
}

// one plane, cooperative across 8 lanes
__device__ __forceinline__ void gather_plane(
    int i, int x0, float wx, int y0, float wy, int p0, float wl,
    int oct, int xl, int yl, int xa, int qa,
    const __half2* __restrict__ s_bh2,
    float& sig, __half2& r0h, __half2& r1h, __half2& r2h)
{
    const uint4* __restrict__ dpu4 = reinterpret_cast<const uint4*>(g_dph);
    const uint4* __restrict__ dlu4 = reinterpret_cast<const uint4*>(g_dlph);
    const uint4* __restrict__ apu4 = reinterpret_cast<const uint4*>(g_aph);
    const uint4* __restrict__ alu4 = reinterpret_cast<const uint4*>(g_alph);

    const __half2 wl2 = __float2half2_rn(wl);

    // ---- density: corner-weight formulation; line lerp = 1 HFMA2 ----
    {
        const float fx = xl ? wx : (1.0f - wx);
        const float fy = yl ? wy : (1.0f - wy);
        const float cw = fx * fy;
        uint4 V  = dpu4[((i * RES + y0 + yl) * RES + x0 + xl) * 2 + oct];
        uint4 L0 = dlu4[(i * RES + p0) * 4 + oct];
        uint4 DL = dlu4[(i * RES + p0) * 4 + 2 + oct];
        const __half2* Vh  = reinterpret_cast<const __half2*>(&V);
        const __half2* L0h = reinterpret_cast<const __half2*>(&L0);
        const __half2* DLh = reinterpret_cast<const __half2*>(&DL);
        __half2 acc = __float2half2_rn(0.0f);
#pragma unroll
        for (int hp = 0; hp < 4; hp++) {
            __half2 lint = __hfma2(DLh[hp], wl2, L0h[hp]);
            acc = __hfma2(Vh[hp], lint, acc);
        }
        float2 af = __half22float2(acc);
        sig += cw * (af.x + af.y);
    }

    // ---- app: lane holds octet qa of column x0+xa, both y rows ----
    {
        const float fxa = xa ? wx : (1.0f - wx);
        const __half2 fxa2 = __float2half2_rn(fxa);
        const __half2 wy2  = __float2half2_rn(wy);
        const __half2 iwy2 = __float2half2_rn(1.0f - wy);
        uint4 A  = apu4[((i * RES + y0) * RES + x0 + xa) * 4 + qa];
        uint4 B  = apu4[((i * RES + y0 + 1) * RES + x0 + xa) * 4 + qa];
        uint4 L0 = alu4[(i * RES + p0) * 8 + qa];
        uint4 DL = alu4[(i * RES + p0) * 8 + 4 + qa];
        const __half2* Ah  = reinterpret_cast<const __half2*>(&A);
        const __half2* Bh  = reinterpret_cast<const __half2*>(&B);
        const __half2* L0h = reinterpret_cast<const __half2*>(&L0);
        const __half2* DLh = reinterpret_cast<const __half2*>(&DL);
        const int bb = i * 16 + qa * 4;
#pragma unroll
        for (int hp = 0; hp < 4; hp++) {
            __half2 m = __hmul2(__hfma2(Bh[hp], wy2, __hmul2(Ah[hp], iwy2)), fxa2);
            __half2 l = __hfma2(DLh[hp], wl2, L0h[hp]);
            __half2 f = __hmul2(m, l);
            r0h = __hfma2(f, s_bh2[bb + hp], r0h);
            r1h = __hfma2(f, s_bh2[48 + bb + hp], r1h);
            r2h = __hfma2(f, s_bh2[96 + bb + hp], r2h);
        }
    }
}

__global__ __launch_bounds__(NS, 3) void render_kernel(
    const float* __restrict__ rays,
    const float* __restrict__ basis,
    const float* __restrict__ aabb,
    float* __restrict__ out) {
    __shared__ __half2 s_bh2[144];        // [k(3)][i(3)][q(4)][hp(4)]
    __shared__ uint4   s_part[NS][9];     // [sample][sub(8)+pad]
    __shared__ float   s_warp[8];
    __shared__ float   s_red[8][5];

    const int ray  = blockIdx.x;
    const int tid  = threadIdx.x;
    const int lane = tid & 31;
    const int wid  = tid >> 5;
    const int g    = lane >> 3;
    const int sub  = lane & 7;
    const int oct  = sub & 1;
    const int xl   = (sub >> 1) & 1;
    const int yl   = sub >> 2;
    const int xa   = sub >> 2;
    const int qa   = sub & 3;

    if (tid < 144) {
        const int k  = tid / 48;
        const int rm = tid - k * 48;
        const int i  = rm >> 4;
        const int r2 = rm & 15;
        const int q  = r2 >> 2;
        const int hp = r2 & 3;
        const int c0 = q * 8 + hp * 2;
        float b0 = (c0 < 24)     ? __ldg(&basis[(i * 24 + c0) * 3 + k])     : 0.0f;
        float b1 = (c0 + 1 < 24) ? __ldg(&basis[(i * 24 + c0 + 1) * 3 + k]) : 0.0f;
        s_bh2[tid] = __floats2half2_rn(b0, b1);
    }

    // ray setup — only fm/fb/zm/t_min survive into phase 1
    float t_min = -1e30f, t_max = 1e30f;
    float fm[3], fb[3];
    {
        float o[3], d[3], a0[3], a1[3];
#pragma unroll
        for (int k = 0; k < 3; k++) {
            o[k]  = __ldg(&rays[ray * 6 + k]);
            d[k]  = __ldg(&rays[ray * 6 + 3 + k]);
            a0[k] = __ldg(&aabb[k]);
            a1[k] = __ldg(&aabb[3 + k]);
        }
#pragma unroll
        for (int k = 0; k < 3; k++) {
            float vk = (fabsf(d[k]) < 1e-6f) ? 1e-6f : d[k];
            float ra = (a1[k] - o[k]) / vk;
            float rb = (a0[k] - o[k]) / vk;
            t_min = fmaxf(t_min, fminf(ra, rb));
            t_max = fminf(t_max, fmaxf(ra, rb));
        }
        t_min = fmaxf(t_min, 0.05f);
        t_max = fmaxf(t_max, t_min + 0.001f);
#pragma unroll
        for (int k = 0; k < 3; k++) {
            float inv = 255.0f / (a1[k] - a0[k]);
            fm[k] = d[k] * inv;
            fb[k] = (o[k] - a0[k]) * inv;
        }
    }
    const float zm = (t_max - t_min) * (1.0f / 255.0f);

    __syncthreads();

    // ---- phase 1: cooperative gather; 2 rounds in flight ----
#pragma unroll 2
    for (int r = 0; r < 8; r++) {
        const int j = wid * 32 + r * 4 + g;
        const float z = fmaf((float)j, zm, t_min);
        int xi0, xi1, xi2; float w0, w1, w2;
        grid_split(fmaf(z, fm[0], fb[0]), w0, xi0);
        grid_split(fmaf(z, fm[1], fb[1]), w1, xi1);
        grid_split(fmaf(z, fm[2], fb[2]), w2, xi2);

        float sig = 0.0f;
        __half2 r0h = __float2half2_rn(0.0f);
        __half2 r1h = r0h, r2h = r0h;
        // MAT_MODE=[(0,1),(0,2),(1,2)], VEC_MODE=[2,1,0]
        gather_plane(0, xi0, w0, xi1, w1, xi2, w2, oct, xl, yl, xa, qa, s_bh2, sig, r0h, r1h, r2h);
        gather_plane(1, xi0, w0, xi2, w2, xi1, w1, oct, xl, yl, xa, qa, s_bh2, sig, r0h, r1h, r2h);
        gather_plane(2, xi1, w1, xi2, w2, xi0, w0, oct, xl, yl, xa, qa, s_bh2, sig, r0h, r1h, r2h);

        uint4 pv;
        pv.x = __float_as_uint(sig);
        pv.y = *reinterpret_cast<unsigned*>(&r0h);
        pv.z = *reinterpret_cast<unsigned*>(&r1h);
        pv.w = *reinterpret_cast<unsigned*>(&r2h);
        s_part[j][sub] = pv;
    }
    __syncthreads();

    // ---- phase 2: reduce partials + compositing (thread = sample) ----
    const int j = tid;
    float sig = 0.0f, r0v = 0.0f, r1v = 0.0f, r2v = 0.0f;
#pragma unroll
    for (int s8 = 0; s8 < 8; s8++) {
        uint4 v = s_part[j][s8];
        sig += __uint_as_float(v.x);
        __half2 h;
        *reinterpret_cast<unsigned*>(&h) = v.y;
        float2 f = __half22float2(h); r0v += f.x + f.y;
        *reinterpret_cast<unsigned*>(&h) = v.z;
        f = __half22float2(h); r1v += f.x + f.y;
        *reinterpret_cast<unsigned*>(&h) = v.w;
        f = __half22float2(h); r2v += f.x + f.y;
    }

    // reload ray data (registers were freed during phase 1)
    float o[3], d[3], a0[3], a1[3];
#pragma unroll
    for (int k = 0; k < 3; k++) {
        o[k]  = __ldg(&rays[ray * 6 + k]);
        d[k]  = __ldg(&rays[ray * 6 + 3 + k]);
        a0[k] = __ldg(&aabb[k]);
        a1[k] = __ldg(&aabb[3 + k]);
    }

    const float s  = (float)j * (1.0f / 255.0f);
    const float z  = t_min * (1.0f - s) + t_max * s;
    const int   ja = (j < 255) ? j : 254;
    const float sA = (float)ja * (1.0f / 255.0f);
    const float sB = (float)(ja + 1) * (1.0f / 255.0f);
    const float dist = (t_min * (1.0f - sB) + t_max * sB)
                     - (t_min * (1.0f - sA) + t_max * sA);
    float cc[3];
#pragma unroll
    for (int k = 0; k < 3; k++) {
        float p = o[k] + d[k] * z;
        cc[k] = (p - a0[k]) / (a1[k] - a0[k]) * 2.0f - 1.0f;
    }
    const bool inside =
        fabsf(cc[0]) <= 1.0f && fabsf(cc[1]) <= 1.0f && fabsf(cc[2]) <= 1.0f;

    if (!inside) { sig = 0.0f; r0v = 0.0f; r1v = 0.0f; r2v = 0.0f; }

    float sp = fmaxf(sig, 0.0f) + log1pf(expf(-fabsf(sig)));
    float alpha = inside ? (1.0f - expf(-sp * dist)) : 0.0f;
    float gg = 1.0f - alpha + 1e-10f;

    float p = gg;
#pragma unroll
    for (int off = 1; off < 32; off <<= 1) {
        float n = __shfl_up_sync(0xffffffffu, p, off);
        if (lane >= off) p *= n;
    }
    if (lane == 31) s_warp[wid] = p;
    __syncthreads();
    float woff = 1.0f;
    for (int w = 0; w < wid; w++) woff *= s_warp[w];
    float pexcl = __shfl_up_sync(0xffffffffu, p, 1);
    if (lane == 0) pexcl = 1.0f;
    const float T = woff * pexcl;
    const float weight = alpha * T;

    float cr0 = weight * (1.0f / (1.0f + expf(-r0v)));
    float cr1 = weight * (1.0f / (1.0f + expf(-r1v)));
    float cr2 = weight * (1.0f / (1.0f + expf(-r2v)));
    float czv = weight * z;
    float cw  = weight;

    float vals[5] = {cr0, cr1, cr2, czv, cw};
#pragma unroll
    for (int k = 0; k < 5; k++) {
#pragma unroll
        for (int off = 16; off > 0; off >>= 1)
            vals[k] += __shfl_xor_sync(0xffffffffu, vals[k], off);
    }
    if (lane == 0) {
#pragma unroll
        for (int k = 0; k < 5; k++) s_red[wid][k] = vals[k];
    }
    __syncthreads();
    if (tid == 0) {
        float sum[5] = {0, 0, 0, 0, 0};
#pragma unroll
        for (int w = 0; w < 8; w++)
#pragma unroll
            for (int k = 0; k < 5; k++) sum[k] += s_red[w][k];
        const float acc = sum[4];
        const float bg  = 1.0f - acc;   // WHITE_BG
        out[ray * 3 + 0] = fminf(fmaxf(sum[0] + bg, 0.0f), 1.0f);
        out[ray * 3 + 1] = fminf(fmaxf(sum[1] + bg, 0.0f), 1.0f);
        out[ray * 3 + 2] = fminf(fmaxf(sum[2] + bg, 0.0f), 1.0f);
        out[N_RAYS * 3 + ray] = sum[3];
    }
}

// ---------------- launch -----------------------------------------------------

extern "C" void kernel_launch(void* const* d_in, const int* in_sizes, int n_in,
                              void* d_out, int out_size) {
    const float* rays  = (const float*)d_in[0];
    const float* dp    = (const float*)d_in[1];
    const float* dl    = (const float*)d_in[2];
    const float* ap    = (const float*)d_in[3];
    const float* al    = (const float*)d_in[4];
    const float* basis = (const float*)d_in[5];
    const float* aabb  = (const float*)d_in[6];
    (void)in_sizes; (void)n_in; (void)out_size;

    prep_kernel<<<1728, 256>>>(dp, ap, dl, al);
    render_kernel<<<N_RAYS, NS>>>(rays, basis, aabb, (float*)d_out);
}

// round 14
// speedup vs baseline: 1.1922x; 1.1922x over previous
#include <cuda_runtime.h>
#include <cuda_fp16.h>
#include <math.h>

// ----------------------------------------------------------------------------
// OctreeRender (TensoRF tri-plane renderer) — fp16 tables, cooperative gather,
// smem partials, delta line tables, batched scattered loads per round.
// Output: float[4096*3] rgb_map then float[4096] depth_map
// ----------------------------------------------------------------------------

#define N_RAYS    4096
#define RES       256
#define NS        256
#define DC        16
#define ACP       32    // app channels padded 24 -> 32

// fp16 channel-last scratch (zero-init; pad channels never written => 0)
__device__ __half g_dph[3 * RES * RES * DC];        // [i][y][x][16]
__device__ __half g_aph[3 * RES * RES * ACP];       // [i][y][x][32]
__device__ __half g_dlph[3 * RES * 2 * DC];         // [i][p][{L0,dL}][16]
__device__ __half g_alph[3 * RES * 2 * ACP];        // [i][p][{L0,dL}][32]

// ---------------- prep: thread-per-texel, no smem ----------------------------

__global__ __launch_bounds__(256) void prep_kernel(
    const float* __restrict__ dp, const float* __restrict__ ap,
    const float* __restrict__ dl, const float* __restrict__ al) {
    const int b = blockIdx.x;
    const int tid = threadIdx.x;

    if (b < 768) {
        const int i = b >> 8;
        const int y = b & 255;
        const int x = tid;
        float v[DC];
#pragma unroll
        for (int c = 0; c < DC; c++)
            v[c] = __ldg(&dp[((i * DC + c) * RES + y) * RES + x]);
        unsigned h[8];
#pragma unroll
        for (int k = 0; k < 8; k++) {
            __half2 t = __floats2half2_rn(v[2 * k], v[2 * k + 1]);
            h[k] = *reinterpret_cast<unsigned*>(&t);
        }
        uint4* outp = reinterpret_cast<uint4*>(g_dph) + ((i * RES + y) * RES + x) * 2;
        outp[0] = make_uint4(h[0], h[1], h[2], h[3]);
        outp[1] = make_uint4(h[4], h[5], h[6], h[7]);
    } else if (b < 1536) {
        const int bb = b - 768;
        const int i = bb >> 8;
        const int y = bb & 255;
        const int x = tid;
        float v[24];
#pragma unroll
        for (int c = 0; c < 24; c++)
            v[c] = __ldg(&ap[((i * 24 + c) * RES + y) * RES + x]);
        unsigned h[16];
#pragma unroll
        for (int k = 0; k < 12; k++) {
            __half2 t = __floats2half2_rn(v[2 * k], v[2 * k + 1]);
            h[k] = *reinterpret_cast<unsigned*>(&t);
        }
#pragma unroll
        for (int k = 12; k < 16; k++) h[k] = 0u;
        uint4* outp = reinterpret_cast<uint4*>(g_aph) + ((i * RES + y) * RES + x) * 4;
        outp[0] = make_uint4(h[0],  h[1],  h[2],  h[3]);
        outp[1] = make_uint4(h[4],  h[5],  h[6],  h[7]);
        outp[2] = make_uint4(h[8],  h[9],  h[10], h[11]);
        outp[3] = make_uint4(h[12], h[13], h[14], h[15]);
    } else {
        const int gtid = (b - 1536) * 256 + tid;   // 0..49151
        if (gtid < 3 * RES * 2 * DC) {
            const int c   = gtid & 15;
            const int pos = (gtid >> 4) & 1;
            const int p   = (gtid >> 5) & 255;
            const int i   = gtid >> 13;
            const int pp  = (p + 1 < 255) ? (p + 1) : 255;
            float l0 = __ldg(&dl[(i * DC + c) * RES + p]);
            float l1 = __ldg(&dl[(i * DC + c) * RES + pp]);
            g_dlph[gtid] = __float2half(pos ? (l1 - l0) : l0);
        }
        {
            const int c   = gtid & 31;
            const int pos = (gtid >> 5) & 1;
            const int p   = (gtid >> 6) & 255;
            const int i   = gtid >> 14;
            const int pp  = (p + 1 < 255) ? (p + 1) : 255;
            float l0 = (c < 24) ? __ldg(&al[(i * 24 + c) * RES + p])  : 0.0f;
            float l1 = (c < 24) ? __ldg(&al[(i * 24 + c) * RES + pp]) : 0.0f;
            g_alph[gtid] = __float2half(pos ? (l1 - l0) : l0);
        }
    }
}

// ---------------- render -----------------------------------------------------

__device__ __forceinline__ void grid_split(float f, float& w, int& i0) {
    float f0 = fminf(fmaxf(floorf(f), 0.0f), 254.0f);
    i0 = (int)f0;
    w  = f - f0;
}

__global__ __launch_bounds__(NS, 3) void render_kernel(
    const float* __restrict__ rays,
    const float* __restrict__ basis,
    const float* __restrict__ aabb,
    float* __restrict__ out) {
    __shared__ __half2 s_bh2[144];        // [k(3)][i(3)][q(4)][hp(4)]
    __shared__ uint4   s_part[NS][9];     // [sample][sub(8)+pad]
    __shared__ float   s_warp[8];
    __shared__ float   s_red[8][5];

    const int ray  = blockIdx.x;
    const int tid  = threadIdx.x;
    const int lane = tid & 31;
    const int wid  = tid >> 5;
    const int g    = lane >> 3;
    const int sub  = lane & 7;
    const int oct  = sub & 1;
    const int xl   = (sub >> 1) & 1;
    const int yl   = sub >> 2;
    const int xa   = sub >> 2;
    const int qa   = sub & 3;

    if (tid < 144) {
        const int k  = tid / 48;
        const int rm = tid - k * 48;
        const int i  = rm >> 4;
        const int r2 = rm & 15;
        const int q  = r2 >> 2;
        const int hp = r2 & 3;
        const int c0 = q * 8 + hp * 2;
        float b0 = (c0 < 24)     ? __ldg(&basis[(i * 24 + c0) * 3 + k])     : 0.0f;
        float b1 = (c0 + 1 < 24) ? __ldg(&basis[(i * 24 + c0 + 1) * 3 + k]) : 0.0f;
        s_bh2[tid] = __floats2half2_rn(b0, b1);
    }

    // ray setup (reference-exact t_min/t_max; affine coeffs for the hot loop)
    float t_min = -1e30f, t_max = 1e30f;
    float fm[3], fb[3];
    float o[3], d[3], a0[3], a1[3];
#pragma unroll
    for (int k = 0; k < 3; k++) {
        o[k]  = __ldg(&rays[ray * 6 + k]);
        d[k]  = __ldg(&rays[ray * 6 + 3 + k]);
        a0[k] = __ldg(&aabb[k]);
        a1[k] = __ldg(&aabb[3 + k]);
    }
#pragma unroll
    for (int k = 0; k < 3; k++) {
        float vk = (fabsf(d[k]) < 1e-6f) ? 1e-6f : d[k];
        float ra = (a1[k] - o[k]) / vk;
        float rb = (a0[k] - o[k]) / vk;
        t_min = fmaxf(t_min, fminf(ra, rb));
        t_max = fminf(t_max, fmaxf(ra, rb));
    }
    t_min = fmaxf(t_min, 0.05f);
    t_max = fmaxf(t_max, t_min + 0.001f);
#pragma unroll
    for (int k = 0; k < 3; k++) {
        float inv = 255.0f / (a1[k] - a0[k]);
        fm[k] = d[k] * inv;
        fb[k] = (o[k] - a0[k]) * inv;
    }
    const float zm = (t_max - t_min) * (1.0f / 255.0f);

    __syncthreads();

    const uint4* __restrict__ dpu4 = reinterpret_cast<const uint4*>(g_dph);
    const uint4* __restrict__ dlu4 = reinterpret_cast<const uint4*>(g_dlph);
    const uint4* __restrict__ apu4 = reinterpret_cast<const uint4*>(g_aph);
    const uint4* __restrict__ alu4 = reinterpret_cast<const uint4*>(g_alph);

    // ---- phase 1: cooperative gather; batch 9 scattered loads per round ----
#pragma unroll 1
    for (int r = 0; r < 8; r++) {
        const int j = wid * 32 + r * 4 + g;
        const float z = fmaf((float)j, zm, t_min);
        int xi0, xi1, xi2; float w0, w1, w2;
        grid_split(fmaf(z, fm[0], fb[0]), w0, xi0);
        grid_split(fmaf(z, fm[1], fb[1]), w1, xi1);
        grid_split(fmaf(z, fm[2], fb[2]), w2, xi2);

        // per-plane (u,v,w): MAT_MODE=[(0,1),(0,2),(1,2)], VEC_MODE=[2,1,0]
        const int pu[3] = {xi0, xi0, xi1};
        const int pv[3] = {xi1, xi2, xi2};
        const int pw[3] = {xi2, xi1, xi0};
        const float wu[3] = {w0, w0, w1};
        const float wv[3] = {w1, w2, w2};
        const float ww[3] = {w2, w1, w0};

        // ---- batch the 9 scattered (L2-latency) loads first ----
        uint4 V[3], A[3], B[3];
#pragma unroll
        for (int p = 0; p < 3; p++) {
            const int dvi = ((p * RES + pv[p] + yl) * RES + pu[p] + xl) * 2 + oct;
            V[p] = dpu4[dvi];
        }
#pragma unroll
        for (int p = 0; p < 3; p++) {
            const int aai = ((p * RES + pv[p]) * RES + pu[p] + xa) * 4 + qa;
            A[p] = apu4[aai];
            B[p] = apu4[aai + RES * 4];
        }

        // ---- per plane: L1-resident line loads + math ----
        float sig = 0.0f;
        __half2 r0h = __float2half2_rn(0.0f);
        __half2 r1h = r0h, r2h = r0h;
#pragma unroll
        for (int p = 0; p < 3; p++) {
            const float wxp = wu[p], wyp = wv[p], wlp = ww[p];
            const __half2 wl2 = __float2half2_rn(wlp);
            // density
            {
                const float fx = xl ? wxp : (1.0f - wxp);
                const float fy = yl ? wyp : (1.0f - wyp);
                const float cw = fx * fy;
                const int li = (p * RES + pw[p]) * 4;
                uint4 L0 = dlu4[li + oct];
                uint4 DL = dlu4[li + 2 + oct];
                const __half2* Vh  = reinterpret_cast<const __half2*>(&V[p]);
                const __half2* L0h = reinterpret_cast<const __half2*>(&L0);
                const __half2* DLh = reinterpret_cast<const __half2*>(&DL);
                __half2 acc = __float2half2_rn(0.0f);
#pragma unroll
                for (int hp = 0; hp < 4; hp++) {
                    __half2 lint = __hfma2(DLh[hp], wl2, L0h[hp]);
                    acc = __hfma2(Vh[hp], lint, acc);
                }
                float2 af = __half22float2(acc);
                sig += cw * (af.x + af.y);
            }
            // app
            {
                const float fxa = xa ? wxp : (1.0f - wxp);
                const __half2 fxa2 = __float2half2_rn(fxa);
                const __half2 wy2  = __float2half2_rn(wyp);
                const __half2 iwy2 = __float2half2_rn(1.0f - wyp);
                const int li = (p * RES + pw[p]) * 8;
                uint4 L0 = alu4[li + qa];
                uint4 DL = alu4[li + 4 + qa];
                const __half2* Ah  = reinterpret_cast<const __half2*>(&A[p]);
                const __half2* Bh  = reinterpret_cast<const __half2*>(&B[p]);
                const __half2* L0h = reinterpret_cast<const __half2*>(&L0);
                const __half2* DLh = reinterpret_cast<const __half2*>(&DL);
                const int bb = p * 16 + qa * 4;
#pragma unroll
                for (int hp = 0; hp < 4; hp++) {
                    __half2 m = __hmul2(__hfma2(Bh[hp], wy2, __hmul2(Ah[hp], iwy2)), fxa2);
                    __half2 l = __hfma2(DLh[hp], wl2, L0h[hp]);
                    __half2 f = __hmul2(m, l);
                    r0h = __hfma2(f, s_bh2[bb + hp], r0h);
                    r1h = __hfma2(f, s_bh2[48 + bb + hp], r1h);
                    r2h = __hfma2(f, s_bh2[96 + bb + hp], r2h);
                }
            }
        }

        uint4 pvv;
        pvv.x = __float_as_uint(sig);
        pvv.y = *reinterpret_cast<unsigned*>(&r0h);
        pvv.z = *reinterpret_cast<unsigned*>(&r1h);
        pvv.w = *reinterpret_cast<unsigned*>(&r2h);
        s_part[j][sub] = pvv;
    }
    __syncthreads();

    // ---- phase 2: reduce partials + compositing (thread = sample) ----
    const int j = tid;
    float sig = 0.0f, r0v = 0.0f, r1v = 0.0f, r2v = 0.0f;
#pragma unroll
    for (int s8 = 0; s8 < 8; s8++) {
        uint4 v = s_part[j][s8];
        sig += __uint_as_float(v.x);
        __half2 h;
        *reinterpret_cast<unsigned*>(&h) = v.y;
        float2 f = __half22float2(h); r0v += f.x + f.y;
        *reinterpret_cast<unsigned*>(&h) = v.z;
        f = __half22float2(h); r1v += f.x + f.y;
        *reinterpret_cast<unsigned*>(&h) = v.w;
        f = __half22float2(h); r2v += f.x + f.y;
    }

    const float s  = (float)j * (1.0f / 255.0f);
    const float z  = t_min * (1.0f - s) + t_max * s;
    const int   ja = (j < 255) ? j : 254;
    const float sA = (float)ja * (1.0f / 255.0f);
    const float sB = (float)(ja + 1) * (1.0f / 255.0f);
    const float dist = (t_min * (1.0f - sB) + t_max * sB)
                     - (t_min * (1.0f - sA) + t_max * sA);
    float cc[3];
#pragma unroll
    for (int k = 0; k < 3; k++) {
        float p = o[k] + d[k] * z;
        cc[k] = (p - a0[k]) / (a1[k] - a0[k]) * 2.0f - 1.0f;
    }
    const bool inside =
        fabsf(cc[0]) <= 1.0f && fabsf(cc[1]) <= 1.0f && fabsf(cc[2]) <= 1.0f;

    if (!inside) { sig = 0.0f; r0v = 0.0f; r1v = 0.0f; r2v = 0.0f; }

    float sp = fmaxf(sig, 0.0f) + log1pf(expf(-fabsf(sig)));
    float alpha = inside ? (1.0f - expf(-sp * dist)) : 0.0f;
    float gg = 1.0f - alpha + 1e-10f;

    float p = gg;
#pragma unroll
    for (int off = 1; off < 32; off <<= 1) {
        float n = __shfl_up_sync(0xffffffffu, p, off);
        if (lane >= off) p *= n;
    }
    if (lane == 31) s_warp[wid] = p;
    __syncthreads();
    float woff = 1.0f;
    for (int w = 0; w < wid; w++) woff *= s_warp[w];
    float pexcl = __shfl_up_sync(0xffffffffu, p, 1);
    if (lane == 0) pexcl = 1.0f;
    const float T = woff * pexcl;
    const float weight = alpha * T;

    float cr0 = weight * (1.0f / (1.0f + expf(-r0v)));
    float cr1 = weight * (1.0f / (1.0f + expf(-r1v)));
    float cr2 = weight * (1.0f / (1.0f + expf(-r2v)));
    float czv = weight * z;
    float cw  = weight;

    float vals[5] = {cr0, cr1, cr2, czv, cw};
#pragma unroll
    for (int k = 0; k < 5; k++) {
#pragma unroll
        for (int off = 16; off > 0; off >>= 1)
            vals[k] += __shfl_xor_sync(0xffffffffu, vals[k], off);
    }
    if (lane == 0) {
#pragma unroll
        for (int k = 0; k < 5; k++) s_red[wid][k] = vals[k];
    }
    __syncthreads();
    if (tid == 0) {
        float sum[5] = {0, 0, 0, 0, 0};
#pragma unroll
        for (int w = 0; w < 8; w++)
#pragma unroll
            for (int k = 0; k < 5; k++) sum[k] += s_red[w][k];
        const float acc = sum[4];
        const float bg  = 1.0f - acc;   // WHITE_BG
        out[ray * 3 + 0] = fminf(fmaxf(sum[0] + bg, 0.0f), 1.0f);
        out[ray * 3 + 1] = fminf(fmaxf(sum[1] + bg, 0.0f), 1.0f);
        out[ray * 3 + 2] = fminf(fmaxf(sum[2] + bg, 0.0f), 1.0f);
        out[N_RAYS * 3 + ray] = sum[3];
    }
}

// ---------------- launch -----------------------------------------------------

extern "C" void kernel_launch(void* const* d_in, const int* in_sizes, int n_in,
                              void* d_out, int out_size) {
    const float* rays  = (const float*)d_in[0];
    const float* dp    = (const float*)d_in[1];
    const float* dl    = (const float*)d_in[2];
    const float* ap    = (const float*)d_in[3];
    const float* al    = (const float*)d_in[4];
    const float* basis = (const float*)d_in[5];
    const float* aabb  = (const float*)d_in[6];
    (void)in_sizes; (void)n_in; (void)out_size;

    prep_kernel<<<1728, 256>>>(dp, ap, dl, al);
    render_kernel<<<N_RAYS, NS>>>(rays, basis, aabb, (float*)d_out);
}

// round 15
// speedup vs baseline: 1.2026x; 1.0088x over previous
#include <cuda_runtime.h>
#include <cuda_fp16.h>
#include <math.h>

// ----------------------------------------------------------------------------
// OctreeRender (TensoRF tri-plane renderer) — fp16 tables, cooperative gather,
// smem partials, delta line tables, batched scattered loads (L2-only via ldcg).
// Output: float[4096*3] rgb_map then float[4096] depth_map
// ----------------------------------------------------------------------------

#define N_RAYS    4096
#define RES       256
#define NS        256
#define DC        16
#define ACP       32    // app channels padded 24 -> 32

// fp16 channel-last scratch (zero-init; pad channels never written => 0)
__device__ __half g_dph[3 * RES * RES * DC];        // [i][y][x][16]
__device__ __half g_aph[3 * RES * RES * ACP];       // [i][y][x][32]
__device__ __half g_dlph[3 * RES * 2 * DC];         // [i][p][{L0,dL}][16]
__device__ __half g_alph[3 * RES * 2 * ACP];        // [i][p][{L0,dL}][32]

// ---------------- prep: thread-per-texel, no smem ----------------------------

__global__ __launch_bounds__(256) void prep_kernel(
    const float* __restrict__ dp, const float* __restrict__ ap,
    const float* __restrict__ dl, const float* __restrict__ al) {
    const int b = blockIdx.x;
    const int tid = threadIdx.x;

    if (b < 768) {
        const int i = b >> 8;
        const int y = b & 255;
        const int x = tid;
        float v[DC];
#pragma unroll
        for (int c = 0; c < DC; c++)
            v[c] = __ldg(&dp[((i * DC + c) * RES + y) * RES + x]);
        unsigned h[8];
#pragma unroll
        for (int k = 0; k < 8; k++) {
            __half2 t = __floats2half2_rn(v[2 * k], v[2 * k + 1]);
            h[k] = *reinterpret_cast<unsigned*>(&t);
        }
        uint4* outp = reinterpret_cast<uint4*>(g_dph) + ((i * RES + y) * RES + x) * 2;
        outp[0] = make_uint4(h[0], h[1], h[2], h[3]);
        outp[1] = make_uint4(h[4], h[5], h[6], h[7]);
    } else if (b < 1536) {
        const int bb = b - 768;
        const int i = bb >> 8;
        const int y = bb & 255;
        const int x = tid;
        float v[24];
#pragma unroll
        for (int c = 0; c < 24; c++)
            v[c] = __ldg(&ap[((i * 24 + c) * RES + y) * RES + x]);
        unsigned h[16];
#pragma unroll
        for (int k = 0; k < 12; k++) {
            __half2 t = __floats2half2_rn(v[2 * k], v[2 * k + 1]);
            h[k] = *reinterpret_cast<unsigned*>(&t);
        }
#pragma unroll
        for (int k = 12; k < 16; k++) h[k] = 0u;
        uint4* outp = reinterpret_cast<uint4*>(g_aph) + ((i * RES + y) * RES + x) * 4;
        outp[0] = make_uint4(h[0],  h[1],  h[2],  h[3]);
        outp[1] = make_uint4(h[4],  h[5],  h[6],  h[7]);
        outp[2] = make_uint4(h[8],  h[9],  h[10], h[11]);
        outp[3] = make_uint4(h[12], h[13], h[14], h[15]);
    } else {
        const int gtid = (b - 1536) * 256 + tid;   // 0..49151
        if (gtid < 3 * RES * 2 * DC) {
            const int c   = gtid & 15;
            const int pos = (gtid >> 4) & 1;
            const int p   = (gtid >> 5) & 255;
            const int i   = gtid >> 13;
            const int pp  = (p + 1 < 255) ? (p + 1) : 255;
            float l0 = __ldg(&dl[(i * DC + c) * RES + p]);
            float l1 = __ldg(&dl[(i * DC + c) * RES + pp]);
            g_dlph[gtid] = __float2half(pos ? (l1 - l0) : l0);
        }
        {
            const int c   = gtid & 31;
            const int pos = (gtid >> 5) & 1;
            const int p   = (gtid >> 6) & 255;
            const int i   = gtid >> 14;
            const int pp  = (p + 1 < 255) ? (p + 1) : 255;
            float l0 = (c < 24) ? __ldg(&al[(i * 24 + c) * RES + p])  : 0.0f;
            float l1 = (c < 24) ? __ldg(&al[(i * 24 + c) * RES + pp]) : 0.0f;
            g_alph[gtid] = __float2half(pos ? (l1 - l0) : l0);
        }
    }
}

// ---------------- render -----------------------------------------------------

__device__ __forceinline__ void grid_split(float f, float& w, int& i0) {
    float f0 = fminf(fmaxf(floorf(f), 0.0f), 254.0f);
    i0 = (int)f0;
    w  = f - f0;
}

__global__ __launch_bounds__(NS, 3) void render_kernel(
    const float* __restrict__ rays,
    const float* __restrict__ basis,
    const float* __restrict__ aabb,
    float* __restrict__ out) {
    __shared__ __half2 s_bh2[144];        // [k(3)][i(3)][q(4)][hp(4)]
    __shared__ uint4   s_part[NS][9];     // [sample][sub(8)+pad]
    __shared__ float   s_warp[8];
    __shared__ float   s_red[8][5];

    const int ray  = blockIdx.x;
    const int tid  = threadIdx.x;
    const int lane = tid & 31;
    const int wid  = tid >> 5;
    const int g    = lane >> 3;
    const int sub  = lane & 7;
    const int oct  = sub & 1;
    const int xl   = (sub >> 1) & 1;
    const int yl   = sub >> 2;
    const int xa   = sub >> 2;
    const int qa   = sub & 3;

    if (tid < 144) {
        const int k  = tid / 48;
        const int rm = tid - k * 48;
        const int i  = rm >> 4;
        const int r2 = rm & 15;
        const int q  = r2 >> 2;
        const int hp = r2 & 3;
        const int c0 = q * 8 + hp * 2;
        float b0 = (c0 < 24)     ? __ldg(&basis[(i * 24 + c0) * 3 + k])     : 0.0f;
        float b1 = (c0 + 1 < 24) ? __ldg(&basis[(i * 24 + c0 + 1) * 3 + k]) : 0.0f;
        s_bh2[tid] = __floats2half2_rn(b0, b1);
    }

    // ray setup (reference-exact t_min/t_max; affine coeffs for the hot loop)
    float t_min = -1e30f, t_max = 1e30f;
    float fm[3], fb[3];
    float o[3], d[3], a0[3], a1[3];
#pragma unroll
    for (int k = 0; k < 3; k++) {
        o[k]  = __ldg(&rays[ray * 6 + k]);
        d[k]  = __ldg(&rays[ray * 6 + 3 + k]);
        a0[k] = __ldg(&aabb[k]);
        a1[k] = __ldg(&aabb[3 + k]);
    }
#pragma unroll
    for (int k = 0; k < 3; k++) {
        float vk = (fabsf(d[k]) < 1e-6f) ? 1e-6f : d[k];
        float ra = (a1[k] - o[k]) / vk;
        float rb = (a0[k] - o[k]) / vk;
        t_min = fmaxf(t_min, fminf(ra, rb));
        t_max = fminf(t_max, fmaxf(ra, rb));
    }
    t_min = fmaxf(t_min, 0.05f);
    t_max = fmaxf(t_max, t_min + 0.001f);
#pragma unroll
    for (int k = 0; k < 3; k++) {
        float inv = 255.0f / (a1[k] - a0[k]);
        fm[k] = d[k] * inv;
        fb[k] = (o[k] - a0[k]) * inv;
    }
    const float zm = (t_max - t_min) * (1.0f / 255.0f);

    __syncthreads();

    const uint4* __restrict__ dpu4 = reinterpret_cast<const uint4*>(g_dph);
    const uint4* __restrict__ dlu4 = reinterpret_cast<const uint4*>(g_dlph);
    const uint4* __restrict__ apu4 = reinterpret_cast<const uint4*>(g_aph);
    const uint4* __restrict__ alu4 = reinterpret_cast<const uint4*>(g_alph);

    // ---- phase 1: cooperative gather; batch 9 scattered loads (L2-only) ----
#pragma unroll 1
    for (int r = 0; r < 8; r++) {
        const int j = wid * 32 + r * 4 + g;
        const float z = fmaf((float)j, zm, t_min);
        int xi0, xi1, xi2; float w0, w1, w2;
        grid_split(fmaf(z, fm[0], fb[0]), w0, xi0);
        grid_split(fmaf(z, fm[1], fb[1]), w1, xi1);
        grid_split(fmaf(z, fm[2], fb[2]), w2, xi2);

        // per-plane (u,v,w): MAT_MODE=[(0,1),(0,2),(1,2)], VEC_MODE=[2,1,0]
        const int pu[3] = {xi0, xi0, xi1};
        const int pv[3] = {xi1, xi2, xi2};
        const int pw[3] = {xi2, xi1, xi0};
        const float wu[3] = {w0, w0, w1};
        const float wv[3] = {w1, w2, w2};
        const float ww[3] = {w2, w1, w0};

        // ---- batch the 9 scattered loads, L2-only (no L1 pollution) ----
        uint4 V[3], A[3], B[3];
#pragma unroll
        for (int p = 0; p < 3; p++) {
            const int dvi = ((p * RES + pv[p] + yl) * RES + pu[p] + xl) * 2 + oct;
            V[p] = __ldcg(&dpu4[dvi]);
        }
#pragma unroll
        for (int p = 0; p < 3; p++) {
            const int aai = ((p * RES + pv[p]) * RES + pu[p] + xa) * 4 + qa;
            A[p] = __ldcg(&apu4[aai]);
            B[p] = __ldcg(&apu4[aai + RES * 4]);
        }

        // ---- per plane: L1-resident line loads + math ----
        float sig = 0.0f;
        __half2 r0h = __float2half2_rn(0.0f);
        __half2 r1h = r0h, r2h = r0h;
#pragma unroll
        for (int p = 0; p < 3; p++) {
            const float wxp = wu[p], wyp = wv[p], wlp = ww[p];
            const __half2 wl2 = __float2half2_rn(wlp);
            // density
            {
                const float fx = xl ? wxp : (1.0f - wxp);
                const float fy = yl ? wyp : (1.0f - wyp);
                const float cw = fx * fy;
                const int li = (p * RES + pw[p]) * 4;
                uint4 L0 = dlu4[li + oct];
                uint4 DL = dlu4[li + 2 + oct];
                const __half2* Vh  = reinterpret_cast<const __half2*>(&V[p]);
                const __half2* L0h = reinterpret_cast<const __half2*>(&L0);
                const __half2* DLh = reinterpret_cast<const __half2*>(&DL);
                __half2 acc = __float2half2_rn(0.0f);
#pragma unroll
                for (int hp = 0; hp < 4; hp++) {
                    __half2 lint = __hfma2(DLh[hp], wl2, L0h[hp]);
                    acc = __hfma2(Vh[hp], lint, acc);
                }
                float2 af = __half22float2(acc);
                sig += cw * (af.x + af.y);
            }
            // app
            {
                const float fxa = xa ? wxp : (1.0f - wxp);
                const __half2 fxa2 = __float2half2_rn(fxa);
                const __half2 wy2  = __float2half2_rn(wyp);
                const __half2 iwy2 = __float2half2_rn(1.0f - wyp);
                const int li = (p * RES + pw[p]) * 8;
                uint4 L0 = alu4[li + qa];
                uint4 DL = alu4[li + 4 + qa];
                const __half2* Ah  = reinterpret_cast<const __half2*>(&A[p]);
                const __half2* Bh  = reinterpret_cast<const __half2*>(&B[p]);
                const __half2* L0h = reinterpret_cast<const __half2*>(&L0);
                const __half2* DLh = reinterpret_cast<const __half2*>(&DL);
                const int bb = p * 16 + qa * 4;
#pragma unroll
                for (int hp = 0; hp < 4; hp++) {
                    __half2 m = __hmul2(__hfma2(Bh[hp], wy2, __hmul2(Ah[hp], iwy2)), fxa2);
                    __half2 l = __hfma2(DLh[hp], wl2, L0h[hp]);
                    __half2 f = __hmul2(m, l);
                    r0h = __hfma2(f, s_bh2[bb + hp], r0h);
                    r1h = __hfma2(f, s_bh2[48 + bb + hp], r1h);
                    r2h = __hfma2(f, s_bh2[96 + bb + hp], r2h);
                }
            }
        }

        uint4 pvv;
        pvv.x = __float_as_uint(sig);
        pvv.y = *reinterpret_cast<unsigned*>(&r0h);
        pvv.z = *reinterpret_cast<unsigned*>(&r1h);
        pvv.w = *reinterpret_cast<unsigned*>(&r2h);
        s_part[j][sub] = pvv;
    }
    __syncthreads();

    // ---- phase 2: reduce partials + compositing (thread = sample) ----
    const int j = tid;
    float sig = 0.0f, r0v = 0.0f, r1v = 0.0f, r2v = 0.0f;
#pragma unroll
    for (int s8 = 0; s8 < 8; s8++) {
        uint4 v = s_part[j][s8];
        sig += __uint_as_float(v.x);
        __half2 h;
        *reinterpret_cast<unsigned*>(&h) = v.y;
        float2 f = __half22float2(h); r0v += f.x + f.y;
        *reinterpret_cast<unsigned*>(&h) = v.z;
        f = __half22float2(h); r1v += f.x + f.y;
        *reinterpret_cast<unsigned*>(&h) = v.w;
        f = __half22float2(h); r2v += f.x + f.y;
    }

    const float s  = (float)j * (1.0f / 255.0f);
    const float z  = t_min * (1.0f - s) + t_max * s;
    const int   ja = (j < 255) ? j : 254;
    const float sA = (float)ja * (1.0f / 255.0f);
    const float sB = (float)(ja + 1) * (1.0f / 255.0f);
    const float dist = (t_min * (1.0f - sB) + t_max * sB)
                     - (t_min * (1.0f - sA) + t_max * sA);
    float cc[3];
#pragma unroll
    for (int k = 0; k < 3; k++) {
        float p = o[k] + d[k] * z;
        cc[k] = (p - a0[k]) / (a1[k] - a0[k]) * 2.0f - 1.0f;
    }
    const bool inside =
        fabsf(cc[0]) <= 1.0f && fabsf(cc[1]) <= 1.0f && fabsf(cc[2]) <= 1.0f;

    if (!inside) { sig = 0.0f; r0v = 0.0f; r1v = 0.0f; r2v = 0.0f; }

    float sp = fmaxf(sig, 0.0f) + log1pf(expf(-fabsf(sig)));
    float alpha = inside ? (1.0f - expf(-sp * dist)) : 0.0f;
    float gg = 1.0f - alpha + 1e-10f;

    float p = gg;
#pragma unroll
    for (int off = 1; off < 32; off <<= 1) {
        float n = __shfl_up_sync(0xffffffffu, p, off);
        if (lane >= off) p *= n;
    }
    if (lane == 31) s_warp[wid] = p;
    __syncthreads();
    float woff = 1.0f;
    for (int w = 0; w < wid; w++) woff *= s_warp[w];
    float pexcl = __shfl_up_sync(0xffffffffu, p, 1);
    if (lane == 0) pexcl = 1.0f;
    const float T = woff * pexcl;
    const float weight = alpha * T;

    float cr0 = weight * (1.0f / (1.0f + expf(-r0v)));
    float cr1 = weight * (1.0f / (1.0f + expf(-r1v)));
    float cr2 = weight * (1.0f / (1.0f + expf(-r2v)));
    float czv = weight * z;
    float cw  = weight;

    float vals[5] = {cr0, cr1, cr2, czv, cw};
#pragma unroll
    for (int k = 0; k < 5; k++) {
#pragma unroll
        for (int off = 16; off > 0; off >>= 1)
            vals[k] += __shfl_xor_sync(0xffffffffu, vals[k], off);
    }
    if (lane == 0) {
#pragma unroll
        for (int k = 0; k < 5; k++) s_red[wid][k] = vals[k];
    }
    __syncthreads();
    if (tid == 0) {
        float sum[5] = {0, 0, 0, 0, 0};
#pragma unroll
        for (int w = 0; w < 8; w++)
#pragma unroll
            for (int k = 0; k < 5; k++) sum[k] += s_red[w][k];
        const float acc = sum[4];
        const float bg  = 1.0f - acc;   // WHITE_BG
        out[ray * 3 + 0] = fminf(fmaxf(sum[0] + bg, 0.0f), 1.0f);
        out[ray * 3 + 1] = fminf(fmaxf(sum[1] + bg, 0.0f), 1.0f);
        out[ray * 3 + 2] = fminf(fmaxf(sum[2] + bg, 0.0f), 1.0f);
        out[N_RAYS * 3 + ray] = sum[3];
    }
}

// ---------------- launch -----------------------------------------------------

extern "C" void kernel_launch(void* const* d_in, const int* in_sizes, int n_in,
                              void* d_out, int out_size) {
    const float* rays  = (const float*)d_in[0];
    const float* dp    = (const float*)d_in[1];
    const float* dl    = (const float*)d_in[2];
    const float* ap    = (const float*)d_in[3];
    const float* al    = (const float*)d_in[4];
    const float* basis = (const float*)d_in[5];
    const float* aabb  = (const float*)d_in[6];
    (void)in_sizes; (void)n_in; (void)out_size;

    prep_kernel<<<1728, 256>>>(dp, ap, dl, al);
    render_kernel<<<N_RAYS, NS>>>(rays, basis, aabb, (float*)d_out);
}